// round 1
// baseline (speedup 1.0000x reference)
#include <cuda_runtime.h>
#include <math.h>

// Problem constants (fixed by the reference: S=4096, E=1024, D=1024)
#define S_LEN 4096
#define E_DIM 1024
#define D_DIM 1024

// Scratch: __device__ globals (no allocation allowed in kernel_launch)
__device__ float g_Q[(size_t)S_LEN * D_DIM];
__device__ float g_K[(size_t)S_LEN * D_DIM];
__device__ float g_V[(size_t)S_LEN * D_DIM];
__device__ float g_P[(size_t)S_LEN * S_LEN];   // scores, then probabilities

// ---------------------------------------------------------------------------
// Tiled fp32 GEMM core: 128x128 tile, BK=16, 256 threads, 8x8 per thread.
// ---------------------------------------------------------------------------
#define BM 128
#define BN 128
#define BK 16

// C[M,N] = A[M,K] @ B[K,N]   (NN). blockIdx.z selects (B, C) pair for QKV.
__global__ __launch_bounds__(256)
void qkv_gemm(const float* __restrict__ A,
              const float* __restrict__ B0, const float* __restrict__ B1,
              const float* __restrict__ B2,
              float* __restrict__ C0, float* __restrict__ C1,
              float* __restrict__ C2)
{
    const int M = S_LEN, N = D_DIM, K = E_DIM;
    const float* B = (blockIdx.z == 0) ? B0 : (blockIdx.z == 1) ? B1 : B2;
    float*       C = (blockIdx.z == 0) ? C0 : (blockIdx.z == 1) ? C1 : C2;

    __shared__ float As[BK][BM];
    __shared__ float Bs[BK][BN];

    const int tid = threadIdx.x;
    const int m0 = blockIdx.y * BM;
    const int n0 = blockIdx.x * BN;

    const int aRow = tid >> 2;          // 0..63
    const int aCol = (tid & 3) << 2;    // 0,4,8,12
    const int bRow = tid >> 5;          // 0..7
    const int bCol = (tid & 31) << 2;   // 0..124

    const int tRow = (tid >> 4) << 3;
    const int tCol = (tid & 15) << 3;

    float acc[8][8];
#pragma unroll
    for (int i = 0; i < 8; i++)
#pragma unroll
        for (int j = 0; j < 8; j++) acc[i][j] = 0.0f;

    for (int k0 = 0; k0 < K; k0 += BK) {
#pragma unroll
        for (int p = 0; p < 2; p++) {
            int r = aRow + p * 64;
            float4 v = *(const float4*)&A[(size_t)(m0 + r) * K + k0 + aCol];
            As[aCol + 0][r] = v.x; As[aCol + 1][r] = v.y;
            As[aCol + 2][r] = v.z; As[aCol + 3][r] = v.w;
        }
#pragma unroll
        for (int p = 0; p < 2; p++) {
            int r = bRow + p * 8;
            *(float4*)&Bs[r][bCol] = *(const float4*)&B[(size_t)(k0 + r) * N + n0 + bCol];
        }
        __syncthreads();
#pragma unroll
        for (int kk = 0; kk < BK; kk++) {
            float4 a0 = *(const float4*)&As[kk][tRow];
            float4 a1 = *(const float4*)&As[kk][tRow + 4];
            float4 b0 = *(const float4*)&Bs[kk][tCol];
            float4 b1 = *(const float4*)&Bs[kk][tCol + 4];
            float ra[8] = {a0.x, a0.y, a0.z, a0.w, a1.x, a1.y, a1.z, a1.w};
            float rb[8] = {b0.x, b0.y, b0.z, b0.w, b1.x, b1.y, b1.z, b1.w};
#pragma unroll
            for (int i = 0; i < 8; i++)
#pragma unroll
                for (int j = 0; j < 8; j++) acc[i][j] += ra[i] * rb[j];
        }
        __syncthreads();
    }

#pragma unroll
    for (int i = 0; i < 8; i++) {
        float4 o0 = make_float4(acc[i][0], acc[i][1], acc[i][2], acc[i][3]);
        float4 o1 = make_float4(acc[i][4], acc[i][5], acc[i][6], acc[i][7]);
        *(float4*)&C[(size_t)(m0 + tRow + i) * N + n0 + tCol]     = o0;
        *(float4*)&C[(size_t)(m0 + tRow + i) * N + n0 + tCol + 4] = o1;
    }
}

// Scores: P[S,S] = (Q[S,D] @ K[S,D]^T) * scale, lower-triangular blocks only.
__global__ __launch_bounds__(256)
void scores_gemm(const float* __restrict__ Q, const float* __restrict__ Km,
                 float* __restrict__ P, float scale)
{
    const int br = blockIdx.y, bc = blockIdx.x;
    if (bc > br) return;   // fully masked block: never written, never read

    const int K = D_DIM, N = S_LEN;
    __shared__ float As[BK][BM];
    __shared__ float Bs[BK][BN];

    const int tid = threadIdx.x;
    const int m0 = br * BM;
    const int n0 = bc * BN;

    const int aRow = tid >> 2;
    const int aCol = (tid & 3) << 2;
    const int tRow = (tid >> 4) << 3;
    const int tCol = (tid & 15) << 3;

    float acc[8][8];
#pragma unroll
    for (int i = 0; i < 8; i++)
#pragma unroll
        for (int j = 0; j < 8; j++) acc[i][j] = 0.0f;

    for (int k0 = 0; k0 < K; k0 += BK) {
#pragma unroll
        for (int p = 0; p < 2; p++) {
            int r = aRow + p * 64;
            float4 v = *(const float4*)&Q[(size_t)(m0 + r) * K + k0 + aCol];
            As[aCol + 0][r] = v.x; As[aCol + 1][r] = v.y;
            As[aCol + 2][r] = v.z; As[aCol + 3][r] = v.w;
            float4 w = *(const float4*)&Km[(size_t)(n0 + r) * K + k0 + aCol];
            Bs[aCol + 0][r] = w.x; Bs[aCol + 1][r] = w.y;
            Bs[aCol + 2][r] = w.z; Bs[aCol + 3][r] = w.w;
        }
        __syncthreads();
#pragma unroll
        for (int kk = 0; kk < BK; kk++) {
            float4 a0 = *(const float4*)&As[kk][tRow];
            float4 a1 = *(const float4*)&As[kk][tRow + 4];
            float4 b0 = *(const float4*)&Bs[kk][tCol];
            float4 b1 = *(const float4*)&Bs[kk][tCol + 4];
            float ra[8] = {a0.x, a0.y, a0.z, a0.w, a1.x, a1.y, a1.z, a1.w};
            float rb[8] = {b0.x, b0.y, b0.z, b0.w, b1.x, b1.y, b1.z, b1.w};
#pragma unroll
            for (int i = 0; i < 8; i++)
#pragma unroll
                for (int j = 0; j < 8; j++) acc[i][j] += ra[i] * rb[j];
        }
        __syncthreads();
    }

#pragma unroll
    for (int i = 0; i < 8; i++) {
        float4 o0 = make_float4(acc[i][0] * scale, acc[i][1] * scale,
                                acc[i][2] * scale, acc[i][3] * scale);
        float4 o1 = make_float4(acc[i][4] * scale, acc[i][5] * scale,
                                acc[i][6] * scale, acc[i][7] * scale);
        *(float4*)&P[(size_t)(m0 + tRow + i) * N + n0 + tCol]     = o0;
        *(float4*)&P[(size_t)(m0 + tRow + i) * N + n0 + tCol + 4] = o1;
    }
}

// Row-wise causal softmax: row i uses j in [0, i]; zeros padded to the
// 128-aligned block end so the PV GEMM's truncated K-loop reads valid data.
__global__ __launch_bounds__(256)
void softmax_rows(float* __restrict__ P)
{
    const int row = blockIdx.x;
    float* p = P + (size_t)row * S_LEN;
    const int len = row + 1;
    const int tid = threadIdx.x;
    const int lane = tid & 31, warp = tid >> 5;
    __shared__ float red[8];
    __shared__ float bcast;

    // pass 1: max
    float m = -3.4e38f;
    for (int j = tid; j < len; j += 256) m = fmaxf(m, p[j]);
#pragma unroll
    for (int o = 16; o; o >>= 1) m = fmaxf(m, __shfl_xor_sync(0xffffffffu, m, o));
    if (lane == 0) red[warp] = m;
    __syncthreads();
    if (tid == 0) {
        float v = red[0];
#pragma unroll
        for (int i = 1; i < 8; i++) v = fmaxf(v, red[i]);
        bcast = v;
    }
    __syncthreads();
    m = bcast;
    __syncthreads();

    // pass 2: exp + sum (store exp in place)
    float s = 0.0f;
    for (int j = tid; j < len; j += 256) {
        float e = expf(p[j] - m);
        p[j] = e;
        s += e;
    }
#pragma unroll
    for (int o = 16; o; o >>= 1) s += __shfl_xor_sync(0xffffffffu, s, o);
    if (lane == 0) red[warp] = s;
    __syncthreads();
    if (tid == 0) {
        float v = 0.0f;
#pragma unroll
        for (int i = 0; i < 8; i++) v += red[i];
        bcast = 1.0f / v;
    }
    __syncthreads();
    const float inv = bcast;

    // pass 3: normalize + zero-pad to block boundary
    for (int j = tid; j < len; j += 256) p[j] *= inv;
    const int kpad = ((row >> 7) + 1) << 7;
    for (int j = len + tid; j < kpad; j += 256) p[j] = 0.0f;
}

// Out[S,D] = P[S,S] @ V[S,D] with causal K-truncation per block row.
__global__ __launch_bounds__(256)
void pv_gemm(const float* __restrict__ P, const float* __restrict__ V,
             float* __restrict__ C)
{
    const int N = D_DIM, K = S_LEN;
    __shared__ float As[BK][BM];
    __shared__ float Bs[BK][BN];

    const int tid = threadIdx.x;
    const int m0 = blockIdx.y * BM;
    const int n0 = blockIdx.x * BN;
    const int kEnd = (blockIdx.y + 1) * BM;  // causal: rows m0..m0+127 need j < kEnd

    const int aRow = tid >> 2;
    const int aCol = (tid & 3) << 2;
    const int bRow = tid >> 5;
    const int bCol = (tid & 31) << 2;
    const int tRow = (tid >> 4) << 3;
    const int tCol = (tid & 15) << 3;

    float acc[8][8];
#pragma unroll
    for (int i = 0; i < 8; i++)
#pragma unroll
        for (int j = 0; j < 8; j++) acc[i][j] = 0.0f;

    for (int k0 = 0; k0 < kEnd; k0 += BK) {
#pragma unroll
        for (int p = 0; p < 2; p++) {
            int r = aRow + p * 64;
            float4 v = *(const float4*)&P[(size_t)(m0 + r) * K + k0 + aCol];
            As[aCol + 0][r] = v.x; As[aCol + 1][r] = v.y;
            As[aCol + 2][r] = v.z; As[aCol + 3][r] = v.w;
        }
#pragma unroll
        for (int p = 0; p < 2; p++) {
            int r = bRow + p * 8;
            *(float4*)&Bs[r][bCol] = *(const float4*)&V[(size_t)(k0 + r) * N + n0 + bCol];
        }
        __syncthreads();
#pragma unroll
        for (int kk = 0; kk < BK; kk++) {
            float4 a0 = *(const float4*)&As[kk][tRow];
            float4 a1 = *(const float4*)&As[kk][tRow + 4];
            float4 b0 = *(const float4*)&Bs[kk][tCol];
            float4 b1 = *(const float4*)&Bs[kk][tCol + 4];
            float ra[8] = {a0.x, a0.y, a0.z, a0.w, a1.x, a1.y, a1.z, a1.w};
            float rb[8] = {b0.x, b0.y, b0.z, b0.w, b1.x, b1.y, b1.z, b1.w};
#pragma unroll
            for (int i = 0; i < 8; i++)
#pragma unroll
                for (int j = 0; j < 8; j++) acc[i][j] += ra[i] * rb[j];
        }
        __syncthreads();
    }

#pragma unroll
    for (int i = 0; i < 8; i++) {
        float4 o0 = make_float4(acc[i][0], acc[i][1], acc[i][2], acc[i][3]);
        float4 o1 = make_float4(acc[i][4], acc[i][5], acc[i][6], acc[i][7]);
        *(float4*)&C[(size_t)(m0 + tRow + i) * N + n0 + tCol]     = o0;
        *(float4*)&C[(size_t)(m0 + tRow + i) * N + n0 + tCol + 4] = o1;
    }
}

extern "C" void kernel_launch(void* const* d_in, const int* in_sizes, int n_in,
                              void* d_out, int out_size)
{
    const float* x  = (const float*)d_in[0];
    const float* Wq = (const float*)d_in[1];
    const float* Wk = (const float*)d_in[2];
    const float* Wv = (const float*)d_in[3];
    float* out = (float*)d_out;

    float *Q, *K, *V, *P;
    cudaGetSymbolAddress((void**)&Q, g_Q);
    cudaGetSymbolAddress((void**)&K, g_K);
    cudaGetSymbolAddress((void**)&V, g_V);
    cudaGetSymbolAddress((void**)&P, g_P);

    // 1) Q/K/V projections
    {
        dim3 grid(D_DIM / BN, S_LEN / BM, 3);
        qkv_gemm<<<grid, 256>>>(x, Wq, Wk, Wv, Q, K, V);
    }
    // 2) causal scores (lower-triangular blocks only), scale = 1/sqrt(1024)
    {
        dim3 grid(S_LEN / BN, S_LEN / BM);
        scores_gemm<<<grid, 256>>>(Q, K, P, 1.0f / 32.0f);
    }
    // 3) row softmax (causal, zero-padded to block boundary)
    softmax_rows<<<S_LEN, 256>>>(P);
    // 4) output = P @ V with causal K-truncation
    {
        dim3 grid(D_DIM / BN, S_LEN / BM);
        pv_gemm<<<grid, 256>>>(P, V, out);
    }
}

// round 3
// speedup vs baseline: 2.7281x; 2.7281x over previous
#include <cuda_runtime.h>
#include <cuda_bf16.h>
#include <cstdint>
#include <math.h>

#define S_LEN 4096
#define E_DIM 1024
#define D_DIM 1024

typedef __nv_bfloat16 bf16;

// ---------------- scratch (device globals; no allocation allowed) ----------
__device__ bf16  g_xh[(size_t)S_LEN * E_DIM];
__device__ bf16  g_xl[(size_t)S_LEN * E_DIM];
__device__ bf16  g_Wth[3][(size_t)D_DIM * E_DIM];   // W^T split hi
__device__ bf16  g_Wtl[3][(size_t)D_DIM * E_DIM];   // W^T split lo
__device__ bf16  g_Qh[(size_t)S_LEN * D_DIM];
__device__ bf16  g_Ql[(size_t)S_LEN * D_DIM];
__device__ bf16  g_Kh[(size_t)S_LEN * D_DIM];
__device__ bf16  g_Kl[(size_t)S_LEN * D_DIM];
__device__ float g_Vf[(size_t)S_LEN * D_DIM];
__device__ bf16  g_Vth[(size_t)D_DIM * S_LEN];      // V^T split hi
__device__ bf16  g_Vtl[(size_t)D_DIM * S_LEN];      // V^T split lo
__device__ float g_Pf[(size_t)S_LEN * S_LEN];       // raw scores (lower tri)
__device__ bf16  g_Ph[(size_t)S_LEN * S_LEN];
__device__ bf16  g_Pl[(size_t)S_LEN * S_LEN];

// ---------------- PTX helpers (sm_80-compatible only) -----------------------
__device__ __forceinline__ uint32_t smem_u32(const void* p) {
    uint32_t a;
    asm("{ .reg .u64 t; cvta.to.shared.u64 t, %1; cvt.u32.u64 %0, t; }" : "=r"(a) : "l"(p));
    return a;
}

#define CP_ASYNC16(saddr, gaddr) \
    asm volatile("cp.async.cg.shared.global [%0], [%1], 16;" \
                 :: "r"(saddr), "l"(gaddr) : "memory")
#define CP_COMMIT() asm volatile("cp.async.commit_group;" ::: "memory")
#define CP_WAIT(N)  asm volatile("cp.async.wait_group %0;" :: "n"(N) : "memory")

#define LDSM4(r0, r1, r2, r3, addr) \
    asm volatile("ldmatrix.sync.aligned.m8n8.x4.shared.b16 {%0,%1,%2,%3}, [%4];" \
                 : "=r"(r0), "=r"(r1), "=r"(r2), "=r"(r3) : "r"(addr))

#define MMA16816(c0, c1, c2, c3, a0, a1, a2, a3, b0, b1) \
    asm volatile("mma.sync.aligned.m16n8k16.row.col.f32.bf16.bf16.f32 " \
                 "{%0,%1,%2,%3}, {%4,%5,%6,%7}, {%8,%9}, {%0,%1,%2,%3};" \
                 : "+f"(c0), "+f"(c1), "+f"(c2), "+f"(c3) \
                 : "r"(a0), "r"(a1), "r"(a2), "r"(a3), "r"(b0), "r"(b1))

// ---------------- aux kernels -----------------------------------------------
__global__ __launch_bounds__(256)
void split_f32(const float* __restrict__ src, bf16* __restrict__ h,
               bf16* __restrict__ l, int n)
{
    for (int i = blockIdx.x * 256 + threadIdx.x; i < n; i += gridDim.x * 256) {
        float v = src[i];
        bf16 a = __float2bfloat16(v);
        h[i] = a;
        l[i] = __float2bfloat16(v - __bfloat162float(a));
    }
}

// dst[c][r] = split(src[r][c]);  src is [R][C] fp32, dst is [C][R] bf16 pair
__global__ __launch_bounds__(256)
void transpose_split(const float* __restrict__ src, bf16* __restrict__ dh,
                     bf16* __restrict__ dl, int R, int C)
{
    __shared__ float t[32][33];
    const int bx = blockIdx.x * 32;  // col of src
    const int by = blockIdx.y * 32;  // row of src
    const int tx = threadIdx.x, ty = threadIdx.y;
#pragma unroll
    for (int j = ty; j < 32; j += 8)
        t[j][tx] = src[(size_t)(by + j) * C + bx + tx];
    __syncthreads();
#pragma unroll
    for (int j = ty; j < 32; j += 8) {
        float v = t[tx][j];
        size_t o = (size_t)(bx + j) * R + by + tx;
        bf16 a = __float2bfloat16(v);
        dh[o] = a;
        dl[o] = __float2bfloat16(v - __bfloat162float(a));
    }
}

// causal softmax over raw scores Pf; writes split-bf16 probs, zero-padded to
// the 128-aligned block boundary (= kEnd consumed by the PV GEMM).
__global__ __launch_bounds__(256)
void softmax_split(float* __restrict__ Pf, bf16* __restrict__ Ph, bf16* __restrict__ Pl)
{
    const int row = blockIdx.x;
    float* p = Pf + (size_t)row * S_LEN;
    bf16* ph = Ph + (size_t)row * S_LEN;
    bf16* pl = Pl + (size_t)row * S_LEN;
    const int len = row + 1;
    const int tid = threadIdx.x, lane = tid & 31, warp = tid >> 5;
    __shared__ float red[8];
    __shared__ float bcast;

    float m = -3.4e38f;
    for (int j = tid; j < len; j += 256) m = fmaxf(m, p[j]);
#pragma unroll
    for (int o = 16; o; o >>= 1) m = fmaxf(m, __shfl_xor_sync(0xffffffffu, m, o));
    if (lane == 0) red[warp] = m;
    __syncthreads();
    if (tid == 0) {
        float v = red[0];
#pragma unroll
        for (int i = 1; i < 8; i++) v = fmaxf(v, red[i]);
        bcast = v;
    }
    __syncthreads();
    m = bcast;
    __syncthreads();

    float s = 0.0f;
    for (int j = tid; j < len; j += 256) {
        float e = expf(p[j] - m);
        p[j] = e;
        s += e;
    }
#pragma unroll
    for (int o = 16; o; o >>= 1) s += __shfl_xor_sync(0xffffffffu, s, o);
    if (lane == 0) red[warp] = s;
    __syncthreads();
    if (tid == 0) {
        float v = 0.0f;
#pragma unroll
        for (int i = 0; i < 8; i++) v += red[i];
        bcast = 1.0f / v;
    }
    __syncthreads();
    const float inv = bcast;

    for (int j = tid; j < len; j += 256) {
        float v = p[j] * inv;
        bf16 a = __float2bfloat16(v);
        ph[j] = a;
        pl[j] = __float2bfloat16(v - __bfloat162float(a));
    }
    const int kpad = ((row >> 7) + 1) << 7;
    const bf16 z = __float2bfloat16(0.0f);
    for (int j = len + tid; j < kpad; j += 256) { ph[j] = z; pl[j] = z; }
}

// ---------------- split-bf16 GEMM via mma.sync -------------------------------
// C[m0:+128, n0:+128] = scale * (Ah+Al) @ (Bh+Bl)^T   (3 of 4 products)
// A rows K-major at m0.., B rows K-major at n0.., row length Ktot.
// mode 0: full K, 2D grid. mode 1: triangular 1D grid (scores).
// mode 2: causal PV, kEnd = (br+1)*128. Output fp32 (Cf) or split bf16 (Ch/Cl).
#define RSB     144                  // smem row stride bytes (128B data + 16B pad)
#define TILE_B  (128 * RSB)          // 18432
#define STAGE_B (4 * TILE_B)         // 73728
#define SMEM_SZ (2 * STAGE_B + 128)  // 147584

__global__ __launch_bounds__(256)
void mm_gemm(const bf16* __restrict__ Ah, const bf16* __restrict__ Al,
             const bf16* __restrict__ Bh, const bf16* __restrict__ Bl,
             float* __restrict__ Cf, bf16* __restrict__ Ch, bf16* __restrict__ Cl,
             int Ktot, int ldc, float scale, int mode)
{
    extern __shared__ char smem[];
    const int tid = threadIdx.x;
    const int wid = tid >> 5;
    const int lane = tid & 31;
    const int wm = wid >> 2;          // 0..1  (64-row slabs)
    const int wn = wid & 3;           // 0..3  (32-col slabs)

    int br, bc;
    if (mode == 1) {
        int t = blockIdx.x;
        br = (int)((sqrtf(8.0f * (float)t + 1.0f) - 1.0f) * 0.5f);
        while ((br + 1) * (br + 2) / 2 <= t) br++;
        while (br * (br + 1) / 2 > t) br--;
        bc = t - br * (br + 1) / 2;
    } else {
        br = blockIdx.y;
        bc = blockIdx.x;
    }
    const int m0 = br * 128, n0 = bc * 128;
    const int kEnd = (mode == 2) ? (br + 1) * 128 : Ktot;
    const int NC = kEnd / 64;

    const uint32_t tiles = (smem_u32(smem) + 127u) & ~127u;

    float acc[4][4][4];
#pragma unroll
    for (int i = 0; i < 4; i++)
#pragma unroll
        for (int j = 0; j < 4; j++)
#pragma unroll
            for (int k = 0; k < 4; k++) acc[i][j][k] = 0.0f;

    auto load_stage = [&](int c) {
        const uint32_t st = tiles + (uint32_t)(c & 1) * STAGE_B;
        const int k0 = c * 64;
        const bf16* srcs[4] = {
            Ah + (size_t)m0 * Ktot + k0,
            Al + (size_t)m0 * Ktot + k0,
            Bh + (size_t)n0 * Ktot + k0,
            Bl + (size_t)n0 * Ktot + k0
        };
#pragma unroll
        for (int t = 0; t < 4; t++) {
#pragma unroll
            for (int j4 = 0; j4 < 4; j4++) {
                int j = tid + j4 * 256;
                int row = j >> 3, ck = j & 7;
                const void* g = srcs[t] + (size_t)row * Ktot + ck * 8;
                uint32_t s = st + (uint32_t)t * TILE_B + row * RSB + ck * 16;
                CP_ASYNC16(s, g);
            }
        }
        CP_COMMIT();
    };

    load_stage(0);

    const int lr15 = lane & 15;
    const int lhi16 = (lane >> 4) * 16;          // A chunk-half byte offset
    const int l7 = lane & 7;
    const int bmat = lane >> 3;                  // 0..3
    const int bnsub = (bmat >> 1) * 8;
    const int bkb = (bmat & 1) * 16;

    for (int c = 0; c < NC; c++) {
        if (c + 1 < NC) { load_stage(c + 1); CP_WAIT(1); }
        else            { CP_WAIT(0); }
        __syncthreads();

        const uint32_t st = tiles + (uint32_t)(c & 1) * STAGE_B;
        const uint32_t aHb = st + (uint32_t)(wm * 64) * RSB;
        const uint32_t aLb = aHb + TILE_B;
        const uint32_t bHb = st + 2u * TILE_B + (uint32_t)(wn * 32) * RSB;
        const uint32_t bLb = bHb + TILE_B;

#pragma unroll
        for (int ks = 0; ks < 4; ks++) {
            const uint32_t akb = (uint32_t)(ks * 32 + lhi16);
            const uint32_t bkb2 = (uint32_t)(ks * 32) + bkb;

            uint32_t ah[4][4], al[4][4], bh[2][4], bl[2][4];
#pragma unroll
            for (int mi = 0; mi < 4; mi++) {
                uint32_t ra = (uint32_t)(mi * 16 + lr15) * RSB + akb;
                LDSM4(ah[mi][0], ah[mi][1], ah[mi][2], ah[mi][3], aHb + ra);
                LDSM4(al[mi][0], al[mi][1], al[mi][2], al[mi][3], aLb + ra);
            }
#pragma unroll
            for (int pi = 0; pi < 2; pi++) {
                uint32_t rb = (uint32_t)(pi * 16 + bnsub + l7) * RSB + bkb2;
                LDSM4(bh[pi][0], bh[pi][1], bh[pi][2], bh[pi][3], bHb + rb);
                LDSM4(bl[pi][0], bl[pi][1], bl[pi][2], bl[pi][3], bLb + rb);
            }
#pragma unroll
            for (int mi = 0; mi < 4; mi++) {
#pragma unroll
                for (int ni = 0; ni < 4; ni++) {
                    const int pi = ni >> 1, j = (ni & 1) * 2;
                    float* a4 = acc[mi][ni];
                    MMA16816(a4[0], a4[1], a4[2], a4[3],
                             ah[mi][0], ah[mi][1], ah[mi][2], ah[mi][3],
                             bh[pi][j], bh[pi][j + 1]);
                    MMA16816(a4[0], a4[1], a4[2], a4[3],
                             ah[mi][0], ah[mi][1], ah[mi][2], ah[mi][3],
                             bl[pi][j], bl[pi][j + 1]);
                    MMA16816(a4[0], a4[1], a4[2], a4[3],
                             al[mi][0], al[mi][1], al[mi][2], al[mi][3],
                             bh[pi][j], bh[pi][j + 1]);
                }
            }
        }
        __syncthreads();
    }

    // epilogue: direct register -> global stores
    const int gr = lane >> 2;
    const int gc = (lane & 3) << 1;
#pragma unroll
    for (int mi = 0; mi < 4; mi++) {
#pragma unroll
        for (int ni = 0; ni < 4; ni++) {
            const int r  = m0 + wm * 64 + mi * 16 + gr;
            const int cc = n0 + wn * 32 + ni * 8 + gc;
            float v0 = acc[mi][ni][0] * scale;
            float v1 = acc[mi][ni][1] * scale;
            float v2 = acc[mi][ni][2] * scale;
            float v3 = acc[mi][ni][3] * scale;
            if (Cf) {
                *(float2*)&Cf[(size_t)r * ldc + cc]       = make_float2(v0, v1);
                *(float2*)&Cf[(size_t)(r + 8) * ldc + cc] = make_float2(v2, v3);
            } else {
                bf16 h0 = __float2bfloat16(v0);
                bf16 h1 = __float2bfloat16(v1);
                bf16 h2 = __float2bfloat16(v2);
                bf16 h3 = __float2bfloat16(v3);
                __nv_bfloat162 lo01, lo23;
                lo01.x = __float2bfloat16(v0 - __bfloat162float(h0));
                lo01.y = __float2bfloat16(v1 - __bfloat162float(h1));
                lo23.x = __float2bfloat16(v2 - __bfloat162float(h2));
                lo23.y = __float2bfloat16(v3 - __bfloat162float(h3));
                __nv_bfloat162 hi01; hi01.x = h0; hi01.y = h1;
                __nv_bfloat162 hi23; hi23.x = h2; hi23.y = h3;
                *(__nv_bfloat162*)&Ch[(size_t)r * ldc + cc]       = hi01;
                *(__nv_bfloat162*)&Cl[(size_t)r * ldc + cc]       = lo01;
                *(__nv_bfloat162*)&Ch[(size_t)(r + 8) * ldc + cc] = hi23;
                *(__nv_bfloat162*)&Cl[(size_t)(r + 8) * ldc + cc] = lo23;
            }
        }
    }
}

// ---------------- host launcher ---------------------------------------------
extern "C" void kernel_launch(void* const* d_in, const int* in_sizes, int n_in,
                              void* d_out, int out_size)
{
    const float* x  = (const float*)d_in[0];
    const float* Wq = (const float*)d_in[1];
    const float* Wk = (const float*)d_in[2];
    const float* Wv = (const float*)d_in[3];
    float* out = (float*)d_out;

    bf16 *xh, *xl, *Wth, *Wtl, *Qh, *Ql, *Kh, *Kl, *Vth, *Vtl, *Ph, *Pl;
    float *Vf, *Pf;
    cudaGetSymbolAddress((void**)&xh,  g_xh);
    cudaGetSymbolAddress((void**)&xl,  g_xl);
    cudaGetSymbolAddress((void**)&Wth, g_Wth);
    cudaGetSymbolAddress((void**)&Wtl, g_Wtl);
    cudaGetSymbolAddress((void**)&Qh,  g_Qh);
    cudaGetSymbolAddress((void**)&Ql,  g_Ql);
    cudaGetSymbolAddress((void**)&Kh,  g_Kh);
    cudaGetSymbolAddress((void**)&Kl,  g_Kl);
    cudaGetSymbolAddress((void**)&Vf,  g_Vf);
    cudaGetSymbolAddress((void**)&Vth, g_Vth);
    cudaGetSymbolAddress((void**)&Vtl, g_Vtl);
    cudaGetSymbolAddress((void**)&Pf,  g_Pf);
    cudaGetSymbolAddress((void**)&Ph,  g_Ph);
    cudaGetSymbolAddress((void**)&Pl,  g_Pl);

    cudaFuncSetAttribute(mm_gemm, cudaFuncAttributeMaxDynamicSharedMemorySize, SMEM_SZ);

    const size_t WSZ = (size_t)D_DIM * E_DIM;

    // 1) split x
    split_f32<<<2048, 256>>>(x, xh, xl, S_LEN * E_DIM);
    // 2) transpose+split weights: W[E,D] -> Wt[D,E]
    {
        dim3 tb(32, 8);
        transpose_split<<<dim3(32, 32), tb>>>(Wq, Wth + 0 * WSZ, Wtl + 0 * WSZ, E_DIM, D_DIM);
        transpose_split<<<dim3(32, 32), tb>>>(Wk, Wth + 1 * WSZ, Wtl + 1 * WSZ, E_DIM, D_DIM);
        transpose_split<<<dim3(32, 32), tb>>>(Wv, Wth + 2 * WSZ, Wtl + 2 * WSZ, E_DIM, D_DIM);
    }
    // 3) projections: Q,K split-bf16 out; V fp32 out
    {
        dim3 g(D_DIM / 128, S_LEN / 128);
        mm_gemm<<<g, 256, SMEM_SZ>>>(xh, xl, Wth + 0 * WSZ, Wtl + 0 * WSZ,
                                     nullptr, Qh, Ql, E_DIM, D_DIM, 1.0f, 0);
        mm_gemm<<<g, 256, SMEM_SZ>>>(xh, xl, Wth + 1 * WSZ, Wtl + 1 * WSZ,
                                     nullptr, Kh, Kl, E_DIM, D_DIM, 1.0f, 0);
        mm_gemm<<<g, 256, SMEM_SZ>>>(xh, xl, Wth + 2 * WSZ, Wtl + 2 * WSZ,
                                     Vf, nullptr, nullptr, E_DIM, D_DIM, 1.0f, 0);
    }
    // 4) transpose+split V: V[S,D] -> Vt[D,S]
    {
        dim3 tb(32, 8);
        transpose_split<<<dim3(D_DIM / 32, S_LEN / 32), tb>>>(Vf, Vth, Vtl, S_LEN, D_DIM);
    }
    // 5) causal scores (lower-tri blocks), scale 1/32, fp32 out
    mm_gemm<<<528, 256, SMEM_SZ>>>(Qh, Ql, Kh, Kl,
                                   Pf, nullptr, nullptr, D_DIM, S_LEN, 1.0f / 32.0f, 1);
    // 6) softmax -> split-bf16 probs (zero-padded to 128 boundary)
    softmax_split<<<S_LEN, 256>>>(Pf, Ph, Pl);
    // 7) out = P @ V  (causal K-truncation per block row)
    {
        dim3 g(D_DIM / 128, S_LEN / 128);
        mm_gemm<<<g, 256, SMEM_SZ>>>(Ph, Pl, Vth, Vtl,
                                     out, nullptr, nullptr, S_LEN, D_DIM, 1.0f, 2);
    }
}

// round 4
// speedup vs baseline: 2.8888x; 1.0589x over previous
#include <cuda_runtime.h>
#include <cuda_bf16.h>
#include <cstdint>
#include <math.h>

#define S_LEN 4096
#define E_DIM 1024
#define D_DIM 1024

typedef __nv_bfloat16 bf16;

// ---------------- scratch (device globals; no allocation allowed) ----------
__device__ bf16  g_xh[(size_t)S_LEN * E_DIM];
__device__ bf16  g_xl[(size_t)S_LEN * E_DIM];
__device__ bf16  g_Wth[3][(size_t)D_DIM * E_DIM];   // W^T split hi (stacked q,k,v)
__device__ bf16  g_Wtl[3][(size_t)D_DIM * E_DIM];   // W^T split lo
__device__ bf16  g_Qh[(size_t)S_LEN * D_DIM];
__device__ bf16  g_Ql[(size_t)S_LEN * D_DIM];
__device__ bf16  g_Kh[(size_t)S_LEN * D_DIM];
__device__ bf16  g_Kl[(size_t)S_LEN * D_DIM];
__device__ float g_Vf[(size_t)S_LEN * D_DIM];
__device__ bf16  g_Vth[(size_t)D_DIM * S_LEN];      // V^T split hi
__device__ bf16  g_Vtl[(size_t)D_DIM * S_LEN];      // V^T split lo
__device__ float g_Pf[(size_t)S_LEN * S_LEN];       // raw scores (lower tri)
__device__ bf16  g_Ph[(size_t)S_LEN * S_LEN];
__device__ bf16  g_Pl[(size_t)S_LEN * S_LEN];

// ---------------- PTX helpers (sm_80-compatible only) -----------------------
__device__ __forceinline__ uint32_t smem_u32(const void* p) {
    uint32_t a;
    asm("{ .reg .u64 t; cvta.to.shared.u64 t, %1; cvt.u32.u64 %0, t; }" : "=r"(a) : "l"(p));
    return a;
}

#define CP_ASYNC16(saddr, gaddr) \
    asm volatile("cp.async.cg.shared.global [%0], [%1], 16;" \
                 :: "r"(saddr), "l"(gaddr) : "memory")
#define CP_COMMIT() asm volatile("cp.async.commit_group;" ::: "memory")
#define CP_WAIT(N)  asm volatile("cp.async.wait_group %0;" :: "n"(N) : "memory")

#define LDSM4(r0, r1, r2, r3, addr) \
    asm volatile("ldmatrix.sync.aligned.m8n8.x4.shared.b16 {%0,%1,%2,%3}, [%4];" \
                 : "=r"(r0), "=r"(r1), "=r"(r2), "=r"(r3) : "r"(addr))

#define MMA16816(c0, c1, c2, c3, a0, a1, a2, a3, b0, b1) \
    asm volatile("mma.sync.aligned.m16n8k16.row.col.f32.bf16.bf16.f32 " \
                 "{%0,%1,%2,%3}, {%4,%5,%6,%7}, {%8,%9}, {%0,%1,%2,%3};" \
                 : "+f"(c0), "+f"(c1), "+f"(c2), "+f"(c3) \
                 : "r"(a0), "r"(a1), "r"(a2), "r"(a3), "r"(b0), "r"(b1))

// ---------------- aux kernels -----------------------------------------------
__global__ __launch_bounds__(256)
void split_f32(const float* __restrict__ src, bf16* __restrict__ h,
               bf16* __restrict__ l, int n)
{
    for (int i = blockIdx.x * 256 + threadIdx.x; i < n; i += gridDim.x * 256) {
        float v = src[i];
        bf16 a = __float2bfloat16(v);
        h[i] = a;
        l[i] = __float2bfloat16(v - __bfloat162float(a));
    }
}

// dst[c][r] = split(src[r][c]);  src is [R][C] fp32, dst is [C][R] bf16 pair
__global__ __launch_bounds__(256)
void transpose_split(const float* __restrict__ src, bf16* __restrict__ dh,
                     bf16* __restrict__ dl, int R, int C)
{
    __shared__ float t[32][33];
    const int bx = blockIdx.x * 32;  // col of src
    const int by = blockIdx.y * 32;  // row of src
    const int tx = threadIdx.x, ty = threadIdx.y;
#pragma unroll
    for (int j = ty; j < 32; j += 8)
        t[j][tx] = src[(size_t)(by + j) * C + bx + tx];
    __syncthreads();
#pragma unroll
    for (int j = ty; j < 32; j += 8) {
        float v = t[tx][j];
        size_t o = (size_t)(bx + j) * R + by + tx;
        bf16 a = __float2bfloat16(v);
        dh[o] = a;
        dl[o] = __float2bfloat16(v - __bfloat162float(a));
    }
}

// causal softmax over raw scores Pf; writes split-bf16 probs, zero-padded to
// the 128-aligned block boundary (= kEnd consumed by the PV GEMM).
__global__ __launch_bounds__(256)
void softmax_split(float* __restrict__ Pf, bf16* __restrict__ Ph, bf16* __restrict__ Pl)
{
    const int row = blockIdx.x;
    float* p = Pf + (size_t)row * S_LEN;
    bf16* ph = Ph + (size_t)row * S_LEN;
    bf16* pl = Pl + (size_t)row * S_LEN;
    const int len = row + 1;
    const int tid = threadIdx.x, lane = tid & 31, warp = tid >> 5;
    __shared__ float red[8];
    __shared__ float bcast;

    float m = -3.4e38f;
    for (int j = tid; j < len; j += 256) m = fmaxf(m, p[j]);
#pragma unroll
    for (int o = 16; o; o >>= 1) m = fmaxf(m, __shfl_xor_sync(0xffffffffu, m, o));
    if (lane == 0) red[warp] = m;
    __syncthreads();
    if (tid == 0) {
        float v = red[0];
#pragma unroll
        for (int i = 1; i < 8; i++) v = fmaxf(v, red[i]);
        bcast = v;
    }
    __syncthreads();
    m = bcast;
    __syncthreads();

    float s = 0.0f;
    for (int j = tid; j < len; j += 256) {
        float e = expf(p[j] - m);
        p[j] = e;
        s += e;
    }
#pragma unroll
    for (int o = 16; o; o >>= 1) s += __shfl_xor_sync(0xffffffffu, s, o);
    if (lane == 0) red[warp] = s;
    __syncthreads();
    if (tid == 0) {
        float v = 0.0f;
#pragma unroll
        for (int i = 0; i < 8; i++) v += red[i];
        bcast = 1.0f / v;
    }
    __syncthreads();
    const float inv = bcast;

    for (int j = tid; j < len; j += 256) {
        float v = p[j] * inv;
        bf16 a = __float2bfloat16(v);
        ph[j] = a;
        pl[j] = __float2bfloat16(v - __bfloat162float(a));
    }
    const int kpad = ((row >> 7) + 1) << 7;
    const bf16 z = __float2bfloat16(0.0f);
    for (int j = len + tid; j < kpad; j += 256) { ph[j] = z; pl[j] = z; }
}

// ---------------- split-bf16 GEMM via mma.sync -------------------------------
// C[m0:+128, n0:+128] = scale * (Ah+Al) @ (Bh+Bl)^T   (3 of 4 products)
// mode 0: fused QKV projection. grid=768 1D: p = t>>8 selects W slab + output.
//         p=0 -> (Qh,Ql) split out; p=1 -> (Kh2,Kl2) split out; p=2 -> Cf=Vf.
// mode 1: triangular 1D grid (scores), fp32 out Cf.
// mode 2: causal PV, kEnd=(br+1)*128, heavy-first zigzag remap, fp32 out Cf.
#define RSB     80                   // smem row stride bytes (64B data + 16B pad)
#define TILE_B  (128 * RSB)          // 10240
#define STAGE_B (4 * TILE_B)         // 40960
#define SMEM_SZ (2 * STAGE_B + 128)  // 82048  -> 2 CTAs/SM

__global__ __launch_bounds__(256, 2)
void mm_gemm(const bf16* __restrict__ Ah, const bf16* __restrict__ Al,
             const bf16* __restrict__ Bh, const bf16* __restrict__ Bl,
             float* __restrict__ Cf, bf16* __restrict__ Ch, bf16* __restrict__ Cl,
             bf16* __restrict__ Kh2, bf16* __restrict__ Kl2,
             int Ktot, int ldc, float scale, int mode)
{
    extern __shared__ char smem[];
    const int tid = threadIdx.x;
    const int wid = tid >> 5;
    const int lane = tid & 31;
    const int wm = wid >> 2;          // 0..1  (64-row slabs)
    const int wn = wid & 3;           // 0..3  (32-col slabs)

    int br, bc, p = 0;
    if (mode == 1) {
        int t = blockIdx.x;
        br = (int)((sqrtf(8.0f * (float)t + 1.0f) - 1.0f) * 0.5f);
        while ((br + 1) * (br + 2) / 2 <= t) br++;
        while (br * (br + 1) / 2 > t) br--;
        bc = t - br * (br + 1) / 2;
    } else if (mode == 2) {
        // heavy-first zigzag: rank r in descending work; pair r with 255-r.
        int t = blockIdx.x;
        int r = (t < 148) ? t : (403 - t);
        br = 31 - (r >> 3);
        bc = r & 7;
    } else {
        int t = blockIdx.x;
        p = t >> 8;
        int r = t & 255;
        br = r >> 3;
        bc = r & 7;
    }
    const int m0 = br * 128, n0 = bc * 128;
    const int kEnd = (mode == 2) ? (br + 1) * 128 : Ktot;
    const int NC = kEnd / 32;

    const bf16* Bhp = Bh + (size_t)p * ((size_t)D_DIM * E_DIM);
    const bf16* Blp = Bl + (size_t)p * ((size_t)D_DIM * E_DIM);

    const uint32_t tiles = (smem_u32(smem) + 127u) & ~127u;

    float acc[4][4][4];
#pragma unroll
    for (int i = 0; i < 4; i++)
#pragma unroll
        for (int j = 0; j < 4; j++)
#pragma unroll
            for (int k = 0; k < 4; k++) acc[i][j][k] = 0.0f;

    auto load_stage = [&](int c) {
        const uint32_t st = tiles + (uint32_t)(c & 1) * STAGE_B;
        const int k0 = c * 32;
        const bf16* srcs[4] = {
            Ah  + (size_t)m0 * Ktot + k0,
            Al  + (size_t)m0 * Ktot + k0,
            Bhp + (size_t)n0 * Ktot + k0,
            Blp + (size_t)n0 * Ktot + k0
        };
#pragma unroll
        for (int t = 0; t < 4; t++) {
#pragma unroll
            for (int j2 = 0; j2 < 2; j2++) {
                int j = tid + j2 * 256;          // 0..511
                int row = j >> 2, ck = j & 3;
                const void* g = srcs[t] + (size_t)row * Ktot + ck * 8;
                uint32_t s = st + (uint32_t)t * TILE_B + row * RSB + ck * 16;
                CP_ASYNC16(s, g);
            }
        }
        CP_COMMIT();
    };

    load_stage(0);

    const int lr15 = lane & 15;
    const int lhi16 = (lane >> 4) * 16;          // A chunk-half byte offset
    const int l7 = lane & 7;
    const int bmat = lane >> 3;                  // 0..3
    const int bnsub = (bmat >> 1) * 8;
    const int bkb = (bmat & 1) * 16;

    for (int c = 0; c < NC; c++) {
        if (c + 1 < NC) { load_stage(c + 1); CP_WAIT(1); }
        else            { CP_WAIT(0); }
        __syncthreads();

        const uint32_t st = tiles + (uint32_t)(c & 1) * STAGE_B;
        const uint32_t aHb = st + (uint32_t)(wm * 64) * RSB;
        const uint32_t aLb = aHb + TILE_B;
        const uint32_t bHb = st + 2u * TILE_B + (uint32_t)(wn * 32) * RSB;
        const uint32_t bLb = bHb + TILE_B;

#pragma unroll
        for (int ks = 0; ks < 2; ks++) {
            const uint32_t akb  = (uint32_t)(ks * 32 + lhi16);
            const uint32_t bkb2 = (uint32_t)(ks * 32) + bkb;

            uint32_t ah[4][4], al[4][4], bh[2][4], bl[2][4];
#pragma unroll
            for (int mi = 0; mi < 4; mi++) {
                uint32_t ra = (uint32_t)(mi * 16 + lr15) * RSB + akb;
                LDSM4(ah[mi][0], ah[mi][1], ah[mi][2], ah[mi][3], aHb + ra);
                LDSM4(al[mi][0], al[mi][1], al[mi][2], al[mi][3], aLb + ra);
            }
#pragma unroll
            for (int pi = 0; pi < 2; pi++) {
                uint32_t rb = (uint32_t)(pi * 16 + bnsub + l7) * RSB + bkb2;
                LDSM4(bh[pi][0], bh[pi][1], bh[pi][2], bh[pi][3], bHb + rb);
                LDSM4(bl[pi][0], bl[pi][1], bl[pi][2], bl[pi][3], bLb + rb);
            }
#pragma unroll
            for (int mi = 0; mi < 4; mi++) {
#pragma unroll
                for (int ni = 0; ni < 4; ni++) {
                    const int pi = ni >> 1, j = (ni & 1) * 2;
                    float* a4 = acc[mi][ni];
                    MMA16816(a4[0], a4[1], a4[2], a4[3],
                             ah[mi][0], ah[mi][1], ah[mi][2], ah[mi][3],
                             bh[pi][j], bh[pi][j + 1]);
                    MMA16816(a4[0], a4[1], a4[2], a4[3],
                             ah[mi][0], ah[mi][1], ah[mi][2], ah[mi][3],
                             bl[pi][j], bl[pi][j + 1]);
                    MMA16816(a4[0], a4[1], a4[2], a4[3],
                             al[mi][0], al[mi][1], al[mi][2], al[mi][3],
                             bh[pi][j], bh[pi][j + 1]);
                }
            }
        }
        __syncthreads();
    }

    // output pointer select
    float* of = Cf;
    bf16 *oh = Ch, *ol = Cl;
    if (mode == 0) {
        if (p == 0)      { of = nullptr; oh = Ch;  ol = Cl;  }
        else if (p == 1) { of = nullptr; oh = Kh2; ol = Kl2; }
        // p == 2: of = Cf (Vf)
    }

    // epilogue: direct register -> global stores
    const int gr = lane >> 2;
    const int gc = (lane & 3) << 1;
#pragma unroll
    for (int mi = 0; mi < 4; mi++) {
#pragma unroll
        for (int ni = 0; ni < 4; ni++) {
            const int r  = m0 + wm * 64 + mi * 16 + gr;
            const int cc = n0 + wn * 32 + ni * 8 + gc;
            float v0 = acc[mi][ni][0] * scale;
            float v1 = acc[mi][ni][1] * scale;
            float v2 = acc[mi][ni][2] * scale;
            float v3 = acc[mi][ni][3] * scale;
            if (of) {
                *(float2*)&of[(size_t)r * ldc + cc]       = make_float2(v0, v1);
                *(float2*)&of[(size_t)(r + 8) * ldc + cc] = make_float2(v2, v3);
            } else {
                bf16 h0 = __float2bfloat16(v0);
                bf16 h1 = __float2bfloat16(v1);
                bf16 h2 = __float2bfloat16(v2);
                bf16 h3 = __float2bfloat16(v3);
                __nv_bfloat162 lo01, lo23;
                lo01.x = __float2bfloat16(v0 - __bfloat162float(h0));
                lo01.y = __float2bfloat16(v1 - __bfloat162float(h1));
                lo23.x = __float2bfloat16(v2 - __bfloat162float(h2));
                lo23.y = __float2bfloat16(v3 - __bfloat162float(h3));
                __nv_bfloat162 hi01; hi01.x = h0; hi01.y = h1;
                __nv_bfloat162 hi23; hi23.x = h2; hi23.y = h3;
                *(__nv_bfloat162*)&oh[(size_t)r * ldc + cc]       = hi01;
                *(__nv_bfloat162*)&ol[(size_t)r * ldc + cc]       = lo01;
                *(__nv_bfloat162*)&oh[(size_t)(r + 8) * ldc + cc] = hi23;
                *(__nv_bfloat162*)&ol[(size_t)(r + 8) * ldc + cc] = lo23;
            }
        }
    }
}

// ---------------- host launcher ---------------------------------------------
extern "C" void kernel_launch(void* const* d_in, const int* in_sizes, int n_in,
                              void* d_out, int out_size)
{
    const float* x  = (const float*)d_in[0];
    const float* Wq = (const float*)d_in[1];
    const float* Wk = (const float*)d_in[2];
    const float* Wv = (const float*)d_in[3];
    float* out = (float*)d_out;

    bf16 *xh, *xl, *Wth, *Wtl, *Qh, *Ql, *Kh, *Kl, *Vth, *Vtl, *Ph, *Pl;
    float *Vf, *Pf;
    cudaGetSymbolAddress((void**)&xh,  g_xh);
    cudaGetSymbolAddress((void**)&xl,  g_xl);
    cudaGetSymbolAddress((void**)&Wth, g_Wth);
    cudaGetSymbolAddress((void**)&Wtl, g_Wtl);
    cudaGetSymbolAddress((void**)&Qh,  g_Qh);
    cudaGetSymbolAddress((void**)&Ql,  g_Ql);
    cudaGetSymbolAddress((void**)&Kh,  g_Kh);
    cudaGetSymbolAddress((void**)&Kl,  g_Kl);
    cudaGetSymbolAddress((void**)&Vf,  g_Vf);
    cudaGetSymbolAddress((void**)&Vth, g_Vth);
    cudaGetSymbolAddress((void**)&Vtl, g_Vtl);
    cudaGetSymbolAddress((void**)&Pf,  g_Pf);
    cudaGetSymbolAddress((void**)&Ph,  g_Ph);
    cudaGetSymbolAddress((void**)&Pl,  g_Pl);

    cudaFuncSetAttribute(mm_gemm, cudaFuncAttributeMaxDynamicSharedMemorySize, SMEM_SZ);

    const size_t WSZ = (size_t)D_DIM * E_DIM;

    // 1) split x
    split_f32<<<2048, 256>>>(x, xh, xl, S_LEN * E_DIM);
    // 2) transpose+split weights: W[E,D] -> Wt[D,E]
    {
        dim3 tb(32, 8);
        transpose_split<<<dim3(32, 32), tb>>>(Wq, Wth + 0 * WSZ, Wtl + 0 * WSZ, E_DIM, D_DIM);
        transpose_split<<<dim3(32, 32), tb>>>(Wk, Wth + 1 * WSZ, Wtl + 1 * WSZ, E_DIM, D_DIM);
        transpose_split<<<dim3(32, 32), tb>>>(Wv, Wth + 2 * WSZ, Wtl + 2 * WSZ, E_DIM, D_DIM);
    }
    // 3) fused QKV projections (one launch): Q,K split out; V fp32 out
    mm_gemm<<<768, 256, SMEM_SZ>>>(xh, xl, Wth, Wtl,
                                   Vf, Qh, Ql, Kh, Kl, E_DIM, D_DIM, 1.0f, 0);
    // 4) transpose+split V: V[S,D] -> Vt[D,S]
    {
        dim3 tb(32, 8);
        transpose_split<<<dim3(D_DIM / 32, S_LEN / 32), tb>>>(Vf, Vth, Vtl, S_LEN, D_DIM);
    }
    // 5) causal scores (lower-tri blocks), scale 1/32, fp32 out
    mm_gemm<<<528, 256, SMEM_SZ>>>(Qh, Ql, Kh, Kl,
                                   Pf, nullptr, nullptr, nullptr, nullptr,
                                   D_DIM, S_LEN, 1.0f / 32.0f, 1);
    // 6) softmax -> split-bf16 probs (zero-padded to 128 boundary)
    softmax_split<<<S_LEN, 256>>>(Pf, Ph, Pl);
    // 7) out = P @ V  (causal, heavy-first zigzag schedule)
    mm_gemm<<<256, 256, SMEM_SZ>>>(Ph, Pl, Vth, Vtl,
                                   out, nullptr, nullptr, nullptr, nullptr,
                                   S_LEN, D_DIM, 1.0f, 2);
}

// round 5
// speedup vs baseline: 3.4611x; 1.1981x over previous
#include <cuda_runtime.h>
#include <cuda_fp16.h>
#include <cstdint>
#include <math.h>

#define S_LEN 4096
#define E_DIM 1024
#define D_DIM 1024

typedef __half h16;

// ---------------- scratch (device globals; no allocation allowed) ----------
__device__ h16   g_xh[(size_t)S_LEN * E_DIM];
__device__ h16   g_xl[(size_t)S_LEN * E_DIM];
__device__ h16   g_Wth[3][(size_t)D_DIM * E_DIM];   // W^T split hi (stacked q,k,v)
__device__ h16   g_Wtl[3][(size_t)D_DIM * E_DIM];   // W^T split lo
__device__ h16   g_Qh[(size_t)S_LEN * D_DIM];
__device__ h16   g_Ql[(size_t)S_LEN * D_DIM];
__device__ h16   g_Kh[(size_t)S_LEN * D_DIM];
__device__ h16   g_Kl[(size_t)S_LEN * D_DIM];
__device__ float g_Vf[(size_t)S_LEN * D_DIM];
__device__ h16   g_Vth[(size_t)D_DIM * S_LEN];      // V^T fp16 (single)
__device__ float g_Pf[(size_t)S_LEN * S_LEN];       // raw scores (lower tri)
__device__ h16   g_Ph[(size_t)S_LEN * S_LEN];       // probs fp16 (single)

// ---------------- PTX helpers (sm_80-compatible only) -----------------------
__device__ __forceinline__ uint32_t smem_u32(const void* p) {
    uint32_t a;
    asm("{ .reg .u64 t; cvta.to.shared.u64 t, %1; cvt.u32.u64 %0, t; }" : "=r"(a) : "l"(p));
    return a;
}

#define CP_ASYNC16(saddr, gaddr) \
    asm volatile("cp.async.cg.shared.global [%0], [%1], 16;" \
                 :: "r"(saddr), "l"(gaddr) : "memory")
#define CP_COMMIT() asm volatile("cp.async.commit_group;" ::: "memory")
#define CP_WAIT(N)  asm volatile("cp.async.wait_group %0;" :: "n"(N) : "memory")

#define LDSM4(r0, r1, r2, r3, addr) \
    asm volatile("ldmatrix.sync.aligned.m8n8.x4.shared.b16 {%0,%1,%2,%3}, [%4];" \
                 : "=r"(r0), "=r"(r1), "=r"(r2), "=r"(r3) : "r"(addr))

#define MMA16816(c0, c1, c2, c3, a0, a1, a2, a3, b0, b1) \
    asm volatile("mma.sync.aligned.m16n8k16.row.col.f32.f16.f16.f32 " \
                 "{%0,%1,%2,%3}, {%4,%5,%6,%7}, {%8,%9}, {%0,%1,%2,%3};" \
                 : "+f"(c0), "+f"(c1), "+f"(c2), "+f"(c3) \
                 : "r"(a0), "r"(a1), "r"(a2), "r"(a3), "r"(b0), "r"(b1))

// ---------------- aux kernels -----------------------------------------------
__global__ __launch_bounds__(256)
void split_f32(const float* __restrict__ src, h16* __restrict__ h,
               h16* __restrict__ l, int n)
{
    for (int i = blockIdx.x * 256 + threadIdx.x; i < n; i += gridDim.x * 256) {
        float v = src[i];
        h16 a = __float2half_rn(v);
        h[i] = a;
        l[i] = __float2half_rn(v - __half2float(a));
    }
}

// dst[c][r] = split(src[r][c]);  dl==nullptr -> single fp16 output
__global__ __launch_bounds__(256)
void transpose_split(const float* __restrict__ src, h16* __restrict__ dh,
                     h16* __restrict__ dl, int R, int C)
{
    __shared__ float t[32][33];
    const int bx = blockIdx.x * 32;  // col of src
    const int by = blockIdx.y * 32;  // row of src
    const int tx = threadIdx.x, ty = threadIdx.y;
#pragma unroll
    for (int j = ty; j < 32; j += 8)
        t[j][tx] = src[(size_t)(by + j) * C + bx + tx];
    __syncthreads();
#pragma unroll
    for (int j = ty; j < 32; j += 8) {
        float v = t[tx][j];
        size_t o = (size_t)(bx + j) * R + by + tx;
        h16 a = __float2half_rn(v);
        dh[o] = a;
        if (dl) dl[o] = __float2half_rn(v - __half2float(a));
    }
}

// causal softmax over raw scores Pf; writes fp16 probs, zero-padded to the
// 128-aligned block boundary (= kEnd consumed by the PV GEMM).
__global__ __launch_bounds__(256)
void softmax_half(float* __restrict__ Pf, h16* __restrict__ Ph)
{
    const int row = blockIdx.x;
    float* p = Pf + (size_t)row * S_LEN;
    h16* ph = Ph + (size_t)row * S_LEN;
    const int len = row + 1;
    const int tid = threadIdx.x, lane = tid & 31, warp = tid >> 5;
    __shared__ float red[8];
    __shared__ float bcast;

    float m = -3.4e38f;
    for (int j = tid; j < len; j += 256) m = fmaxf(m, p[j]);
#pragma unroll
    for (int o = 16; o; o >>= 1) m = fmaxf(m, __shfl_xor_sync(0xffffffffu, m, o));
    if (lane == 0) red[warp] = m;
    __syncthreads();
    if (tid == 0) {
        float v = red[0];
#pragma unroll
        for (int i = 1; i < 8; i++) v = fmaxf(v, red[i]);
        bcast = v;
    }
    __syncthreads();
    m = bcast;
    __syncthreads();

    float s = 0.0f;
    for (int j = tid; j < len; j += 256) {
        float e = expf(p[j] - m);
        p[j] = e;
        s += e;
    }
#pragma unroll
    for (int o = 16; o; o >>= 1) s += __shfl_xor_sync(0xffffffffu, s, o);
    if (lane == 0) red[warp] = s;
    __syncthreads();
    if (tid == 0) {
        float v = 0.0f;
#pragma unroll
        for (int i = 0; i < 8; i++) v += red[i];
        bcast = 1.0f / v;
    }
    __syncthreads();
    const float inv = bcast;

    for (int j = tid; j < len; j += 256)
        ph[j] = __float2half_rn(p[j] * inv);
    const int kpad = ((row >> 7) + 1) << 7;
    const h16 z = __float2half_rn(0.0f);
    for (int j = len + tid; j < kpad; j += 256) ph[j] = z;
}

// ---------------- split-fp16 GEMM via mma.sync -------------------------------
// NPROD=3: C = scale * (AhBh + AhBl + AlBh)   NPROD=1: C = scale * AhBh
// mode 0: fused QKV projection, grid=768: p=t>>8 -> {Q split, K split, Vf}.
// mode 1: triangular 1D grid (scores), fp32 out Cf.
// mode 2: causal PV, kEnd=(br+1)*128, heavy-first zigzag remap, fp32 out Cf.
#define RSB     80                   // smem row stride bytes (64B data + 16B pad)
#define TILE_B  (128 * RSB)          // 10240

template <int NPROD>
__global__ __launch_bounds__(256, 2)
void mm_gemm(const h16* __restrict__ Ah, const h16* __restrict__ Al,
             const h16* __restrict__ Bh, const h16* __restrict__ Bl,
             float* __restrict__ Cf, h16* __restrict__ Ch, h16* __restrict__ Cl,
             h16* __restrict__ Kh2, h16* __restrict__ Kl2,
             int Ktot, int ldc, float scale, int mode)
{
    constexpr int NTILES  = (NPROD == 3) ? 4 : 2;
    constexpr uint32_t STAGE_B = NTILES * TILE_B;

    extern __shared__ char smem[];
    const int tid = threadIdx.x;
    const int wid = tid >> 5;
    const int lane = tid & 31;
    const int wm = wid >> 2;          // 0..1  (64-row slabs)
    const int wn = wid & 3;           // 0..3  (32-col slabs)

    int br, bc, p = 0;
    if (mode == 1) {
        int t = blockIdx.x;
        br = (int)((sqrtf(8.0f * (float)t + 1.0f) - 1.0f) * 0.5f);
        while ((br + 1) * (br + 2) / 2 <= t) br++;
        while (br * (br + 1) / 2 > t) br--;
        bc = t - br * (br + 1) / 2;
    } else if (mode == 2) {
        int t = blockIdx.x;
        int r = (t < 148) ? t : (403 - t);
        br = 31 - (r >> 3);
        bc = r & 7;
    } else {
        int t = blockIdx.x;
        p = t >> 8;
        int r = t & 255;
        br = r >> 3;
        bc = r & 7;
    }
    const int m0 = br * 128, n0 = bc * 128;
    const int kEnd = (mode == 2) ? (br + 1) * 128 : Ktot;
    const int NC = kEnd / 32;

    const h16* Bhp = Bh + (size_t)p * ((size_t)D_DIM * E_DIM);
    const h16* Blp = (NPROD == 3) ? (Bl + (size_t)p * ((size_t)D_DIM * E_DIM)) : nullptr;

    const uint32_t tiles = (smem_u32(smem) + 127u) & ~127u;

    float acc[4][4][4];
#pragma unroll
    for (int i = 0; i < 4; i++)
#pragma unroll
        for (int j = 0; j < 4; j++)
#pragma unroll
            for (int k = 0; k < 4; k++) acc[i][j][k] = 0.0f;

    auto load_stage = [&](int c) {
        const uint32_t st = tiles + (uint32_t)(c & 1) * STAGE_B;
        const int k0 = c * 32;
        const h16* srcs[NTILES];
        if (NPROD == 3) {
            srcs[0] = Ah  + (size_t)m0 * Ktot + k0;
            srcs[1] = Al  + (size_t)m0 * Ktot + k0;
            srcs[2] = Bhp + (size_t)n0 * Ktot + k0;
            srcs[3] = Blp + (size_t)n0 * Ktot + k0;
        } else {
            srcs[0] = Ah  + (size_t)m0 * Ktot + k0;
            srcs[1] = Bhp + (size_t)n0 * Ktot + k0;
        }
#pragma unroll
        for (int t = 0; t < NTILES; t++) {
#pragma unroll
            for (int j2 = 0; j2 < 2; j2++) {
                int j = tid + j2 * 256;          // 0..511
                int row = j >> 2, ck = j & 3;
                const void* g = srcs[t] + (size_t)row * Ktot + ck * 8;
                uint32_t s = st + (uint32_t)t * TILE_B + row * RSB + ck * 16;
                CP_ASYNC16(s, g);
            }
        }
        CP_COMMIT();
    };

    load_stage(0);

    const int lr15 = lane & 15;
    const int lhi16 = (lane >> 4) * 16;          // A chunk-half byte offset
    const int l7 = lane & 7;
    const int bmat = lane >> 3;                  // 0..3
    const int bnsub = (bmat >> 1) * 8;
    const int bkb = (bmat & 1) * 16;

    for (int c = 0; c < NC; c++) {
        if (c + 1 < NC) { load_stage(c + 1); CP_WAIT(1); }
        else            { CP_WAIT(0); }
        __syncthreads();

        const uint32_t st = tiles + (uint32_t)(c & 1) * STAGE_B;
        const uint32_t aHb = st + (uint32_t)(wm * 64) * RSB;
        const uint32_t aLb = aHb + TILE_B;                       // NPROD==3 only
        const uint32_t bHb = st + (uint32_t)(NTILES / 2) * TILE_B
                                + (uint32_t)(wn * 32) * RSB;
        const uint32_t bLb = bHb + TILE_B;                       // NPROD==3 only

#pragma unroll
        for (int ks = 0; ks < 2; ks++) {
            const uint32_t akb  = (uint32_t)(ks * 32 + lhi16);
            const uint32_t bkb2 = (uint32_t)(ks * 32) + bkb;

            uint32_t ah[4][4], al[4][4], bh[2][4], bl[2][4];
#pragma unroll
            for (int mi = 0; mi < 4; mi++) {
                uint32_t ra = (uint32_t)(mi * 16 + lr15) * RSB + akb;
                LDSM4(ah[mi][0], ah[mi][1], ah[mi][2], ah[mi][3], aHb + ra);
                if (NPROD == 3)
                    LDSM4(al[mi][0], al[mi][1], al[mi][2], al[mi][3], aLb + ra);
            }
#pragma unroll
            for (int pi = 0; pi < 2; pi++) {
                uint32_t rb = (uint32_t)(pi * 16 + bnsub + l7) * RSB + bkb2;
                LDSM4(bh[pi][0], bh[pi][1], bh[pi][2], bh[pi][3], bHb + rb);
                if (NPROD == 3)
                    LDSM4(bl[pi][0], bl[pi][1], bl[pi][2], bl[pi][3], bLb + rb);
            }
#pragma unroll
            for (int mi = 0; mi < 4; mi++) {
#pragma unroll
                for (int ni = 0; ni < 4; ni++) {
                    const int pi = ni >> 1, j = (ni & 1) * 2;
                    float* a4 = acc[mi][ni];
                    MMA16816(a4[0], a4[1], a4[2], a4[3],
                             ah[mi][0], ah[mi][1], ah[mi][2], ah[mi][3],
                             bh[pi][j], bh[pi][j + 1]);
                    if (NPROD == 3) {
                        MMA16816(a4[0], a4[1], a4[2], a4[3],
                                 ah[mi][0], ah[mi][1], ah[mi][2], ah[mi][3],
                                 bl[pi][j], bl[pi][j + 1]);
                        MMA16816(a4[0], a4[1], a4[2], a4[3],
                                 al[mi][0], al[mi][1], al[mi][2], al[mi][3],
                                 bh[pi][j], bh[pi][j + 1]);
                    }
                }
            }
        }
        __syncthreads();
    }

    // output pointer select
    float* of = Cf;
    h16 *oh = Ch, *ol = Cl;
    if (mode == 0) {
        if (p == 0)      { of = nullptr; oh = Ch;  ol = Cl;  }
        else if (p == 1) { of = nullptr; oh = Kh2; ol = Kl2; }
        // p == 2: of = Cf (Vf)
    }

    // epilogue: direct register -> global stores
    const int gr = lane >> 2;
    const int gc = (lane & 3) << 1;
#pragma unroll
    for (int mi = 0; mi < 4; mi++) {
#pragma unroll
        for (int ni = 0; ni < 4; ni++) {
            const int r  = m0 + wm * 64 + mi * 16 + gr;
            const int cc = n0 + wn * 32 + ni * 8 + gc;
            float v0 = acc[mi][ni][0] * scale;
            float v1 = acc[mi][ni][1] * scale;
            float v2 = acc[mi][ni][2] * scale;
            float v3 = acc[mi][ni][3] * scale;
            if (of) {
                *(float2*)&of[(size_t)r * ldc + cc]       = make_float2(v0, v1);
                *(float2*)&of[(size_t)(r + 8) * ldc + cc] = make_float2(v2, v3);
            } else {
                h16 h0 = __float2half_rn(v0);
                h16 h1 = __float2half_rn(v1);
                h16 h2 = __float2half_rn(v2);
                h16 h3 = __float2half_rn(v3);
                __half2 hi01 = __halves2half2(h0, h1);
                __half2 hi23 = __halves2half2(h2, h3);
                __half2 lo01 = __halves2half2(
                    __float2half_rn(v0 - __half2float(h0)),
                    __float2half_rn(v1 - __half2float(h1)));
                __half2 lo23 = __halves2half2(
                    __float2half_rn(v2 - __half2float(h2)),
                    __float2half_rn(v3 - __half2float(h3)));
                *(__half2*)&oh[(size_t)r * ldc + cc]       = hi01;
                *(__half2*)&ol[(size_t)r * ldc + cc]       = lo01;
                *(__half2*)&oh[(size_t)(r + 8) * ldc + cc] = hi23;
                *(__half2*)&ol[(size_t)(r + 8) * ldc + cc] = lo23;
            }
        }
    }
}

#define SMEM3 (2 * 4 * TILE_B + 128)   // 82048
#define SMEM1 (2 * 2 * TILE_B + 128)   // 41088

// ---------------- host launcher ---------------------------------------------
extern "C" void kernel_launch(void* const* d_in, const int* in_sizes, int n_in,
                              void* d_out, int out_size)
{
    const float* x  = (const float*)d_in[0];
    const float* Wq = (const float*)d_in[1];
    const float* Wk = (const float*)d_in[2];
    const float* Wv = (const float*)d_in[3];
    float* out = (float*)d_out;

    h16 *xh, *xl, *Wth, *Wtl, *Qh, *Ql, *Kh, *Kl, *Vth, *Ph;
    float *Vf, *Pf;
    cudaGetSymbolAddress((void**)&xh,  g_xh);
    cudaGetSymbolAddress((void**)&xl,  g_xl);
    cudaGetSymbolAddress((void**)&Wth, g_Wth);
    cudaGetSymbolAddress((void**)&Wtl, g_Wtl);
    cudaGetSymbolAddress((void**)&Qh,  g_Qh);
    cudaGetSymbolAddress((void**)&Ql,  g_Ql);
    cudaGetSymbolAddress((void**)&Kh,  g_Kh);
    cudaGetSymbolAddress((void**)&Kl,  g_Kl);
    cudaGetSymbolAddress((void**)&Vf,  g_Vf);
    cudaGetSymbolAddress((void**)&Vth, g_Vth);
    cudaGetSymbolAddress((void**)&Pf,  g_Pf);
    cudaGetSymbolAddress((void**)&Ph,  g_Ph);

    cudaFuncSetAttribute(mm_gemm<3>, cudaFuncAttributeMaxDynamicSharedMemorySize, SMEM3);
    cudaFuncSetAttribute(mm_gemm<1>, cudaFuncAttributeMaxDynamicSharedMemorySize, SMEM1);

    const size_t WSZ = (size_t)D_DIM * E_DIM;

    // 1) split x
    split_f32<<<2048, 256>>>(x, xh, xl, S_LEN * E_DIM);
    // 2) transpose+split weights: W[E,D] -> Wt[D,E]
    {
        dim3 tb(32, 8);
        transpose_split<<<dim3(32, 32), tb>>>(Wq, Wth + 0 * WSZ, Wtl + 0 * WSZ, E_DIM, D_DIM);
        transpose_split<<<dim3(32, 32), tb>>>(Wk, Wth + 1 * WSZ, Wtl + 1 * WSZ, E_DIM, D_DIM);
        transpose_split<<<dim3(32, 32), tb>>>(Wv, Wth + 2 * WSZ, Wtl + 2 * WSZ, E_DIM, D_DIM);
    }
    // 3) fused QKV projections (one launch): Q,K split out; V fp32 out
    mm_gemm<3><<<768, 256, SMEM3>>>(xh, xl, Wth, Wtl,
                                    Vf, Qh, Ql, Kh, Kl, E_DIM, D_DIM, 1.0f, 0);
    // 4) transpose V: V[S,D] -> Vt[D,S], single fp16
    {
        dim3 tb(32, 8);
        transpose_split<<<dim3(D_DIM / 32, S_LEN / 32), tb>>>(Vf, Vth, nullptr, S_LEN, D_DIM);
    }
    // 5) causal scores (lower-tri blocks), scale 1/32, fp32 out
    mm_gemm<3><<<528, 256, SMEM3>>>(Qh, Ql, Kh, Kl,
                                    Pf, nullptr, nullptr, nullptr, nullptr,
                                    D_DIM, S_LEN, 1.0f / 32.0f, 1);
    // 6) softmax -> fp16 probs (zero-padded to 128 boundary)
    softmax_half<<<S_LEN, 256>>>(Pf, Ph);
    // 7) out = P @ V  (causal, single-product fp16, heavy-first zigzag)
    mm_gemm<1><<<256, 256, SMEM1>>>(Ph, nullptr, Vth, nullptr,
                                    out, nullptr, nullptr, nullptr, nullptr,
                                    S_LEN, D_DIM, 1.0f, 2);
}